// round 5
// baseline (speedup 1.0000x reference)
// Generator_causal on GB300 (compiled at compute_103 baseline — no tcgen05 available,
// so tensor work goes through warp-level mma.sync bf16 + ldmatrix).
// CTA = 128 batch rows, 256 threads (8 warps), 64 sequential node-steps per CTA.
// Warp tiling: 4 row-groups x 2 col-halves; each warp owns 32 rows x 64 cols.
#include <cuda_runtime.h>
#include <cuda_bf16.h>
#include <cstdint>

#define NTH    256
#define TILE_M 128

// ---------------- SMEM map (bytes); matrix tiles 1024-aligned ----------------
#define OFF_ACTA   1024u      // 128x128 bf16 blocked SW128 (32768)
#define OFF_WIB    33792u     // 2 x (128x64 bf16 blocked SW128, 16384)
#define OFF_WS1    66560u     // 128x128 bf16 blocked SW128
#define OFF_WS2    99328u     // 128x128 bf16 blocked SW128
#define OFF_OUTST  132096u    // 128x65 f32 out-state (stride 65) 33280
#define OFF_ZS     165376u    // 128x65 f32 z (stride 65) 33280
#define OFF_MT     198656u    // 64x64 f32 M^T 16384
#define OFF_WIC    215040u    // 2 x 128 f32 (Wi z-column, double buffered)
#define OFF_WFS    216064u    // 128 f32
#define OFF_BIS    216576u    // 128 f32
#define OFF_BS1    217088u    // 128 f32
#define OFF_BS2    217600u    // 128 f32
#define OFF_PART   218112u    // 2 x 128 f32 head partials
#define SMEM_TOTAL 219136u

// ---------------- helpers ----------------
__device__ __forceinline__ uint32_t smem_u32(const void* p) {
    uint32_t a;
    asm("{ .reg .u64 t; cvta.to.shared.u64 t, %1; cvt.u32.u64 %0, t; }" : "=r"(a) : "l"(p));
    return a;
}
// Blocked SW128 byte offset for [rows x K] bf16 K-major tile:
// atom = 8 rows x 64 bf16 (1024B), atom-column stride = 16 atoms (128 rows).
__device__ __forceinline__ uint32_t act_off(int m, int k) {
    uint32_t b = ((uint32_t)(m >> 3) + (uint32_t)(k >> 6) * 16u) * 1024u
               + (uint32_t)(m & 7) * 128u + (uint32_t)(k & 63) * 2u;
    return b ^ ((b >> 3) & 0x70u);
}
__device__ __forceinline__ uint32_t pack2(float a, float b) {
    __nv_bfloat162 t = __floats2bfloat162_rn(a, b);
    return *reinterpret_cast<uint32_t*>(&t);
}
__device__ __forceinline__ void sts32(uint32_t addr, uint32_t v) {
    asm volatile("st.shared.b32 [%0], %1;" :: "r"(addr), "r"(v) : "memory");
}
__device__ __forceinline__ void sts_v2(uint32_t addr, uint32_t lo, uint32_t hi) {
    asm volatile("st.shared.v2.b32 [%0], {%1, %2};" :: "r"(addr), "r"(lo), "r"(hi) : "memory");
}
__device__ __forceinline__ void sts_b16(uint32_t addr, uint16_t v) {
    asm volatile("st.shared.b16 [%0], %1;" :: "r"(addr), "h"(v) : "memory");
}
__device__ __forceinline__ void ldsm4(uint32_t addr, uint32_t* r) {
    asm volatile("ldmatrix.sync.aligned.m8n8.x4.shared.b16 {%0,%1,%2,%3}, [%4];"
                 : "=r"(r[0]), "=r"(r[1]), "=r"(r[2]), "=r"(r[3]) : "r"(addr));
}
__device__ __forceinline__ void mma16816(float* c, const uint32_t* a, uint32_t b0, uint32_t b1) {
    asm volatile("mma.sync.aligned.m16n8k16.row.col.f32.bf16.bf16.f32 "
                 "{%0,%1,%2,%3}, {%4,%5,%6,%7}, {%8,%9}, {%0,%1,%2,%3};"
                 : "+f"(c[0]), "+f"(c[1]), "+f"(c[2]), "+f"(c[3])
                 : "r"(a[0]), "r"(a[1]), "r"(a[2]), "r"(a[3]), "r"(b0), "r"(b1));
}
#define PAIRBAR(id) asm volatile("bar.sync %0, 64;" :: "r"(id) : "memory")

// C[32x64] (warp tile) = A[rows mrow0..+31, 0..16K) @ W[rows ncol0..+63, 0..16K)^T
template<int KSTEPS>
__device__ __forceinline__ void gemm_warp(uint32_t aBase, uint32_t bBase,
                                          int mrow0, int ncol0, int lane,
                                          float acc[16][4]) {
    #pragma unroll
    for (int t = 0; t < 16; t++) {
        acc[t][0] = 0.f; acc[t][1] = 0.f; acc[t][2] = 0.f; acc[t][3] = 0.f;
    }
    const int lr = lane & 7, lt = (lane >> 3) & 1, lh = lane >> 4;
    #pragma unroll
    for (int ks = 0; ks < KSTEPS; ks++) {
        const int k0 = ks * 16;
        uint32_t a[2][4];
        #pragma unroll
        for (int mt = 0; mt < 2; mt++)
            ldsm4(aBase + act_off(mrow0 + 16 * mt + lr + lt * 8, k0 + lh * 8), a[mt]);
        #pragma unroll
        for (int nj = 0; nj < 4; nj++) {
            uint32_t b[4];
            ldsm4(bBase + act_off(ncol0 + 16 * nj + lr + lh * 8, k0 + lt * 8), b);
            #pragma unroll
            for (int mt = 0; mt < 2; mt++) {
                mma16816(acc[mt * 8 + 2 * nj],     a[mt], b[0], b[1]);
                mma16816(acc[mt * 8 + 2 * nj + 1], a[mt], b[2], b[3]);
            }
        }
    }
}

// Stream Wi[step] (128x65 f32) into bf16 SW128 tile buffer `buf` + z-column.
__device__ __forceinline__ void load_wi(const float* __restrict__ Wi, int step,
                                        uint32_t sb, char* smem, int buf, int tid) {
    const float* src = Wi + (size_t)step * 8320;
    const uint32_t wib = sb + OFF_WIB + (uint32_t)buf * 16384u;
    float* wicb = reinterpret_cast<float*>(smem + OFF_WIC) + buf * 128;
    #pragma unroll
    for (int it = 0; it < 33; it++) {
        int idx = it * NTH + tid;
        if (idx < 8320) {
            float v = __ldg(src + idx);
            int n = idx / 65, k = idx - n * 65;
            if (k < 64) {
                __nv_bfloat16 h = __float2bfloat16_rn(v);
                sts_b16(wib + act_off(n, k), *reinterpret_cast<uint16_t*>(&h));
            } else {
                wicb[n] = v;
            }
        }
    }
}

__global__ void __launch_bounds__(NTH, 1)
gen_causal_kernel(const float* __restrict__ x,   const float* __restrict__ z,
                  const float* __restrict__ Mg,  const float* __restrict__ Wi,
                  const float* __restrict__ bi,  const float* __restrict__ Ws1,
                  const float* __restrict__ bs1, const float* __restrict__ Ws2,
                  const float* __restrict__ bs2, const float* __restrict__ wf,
                  const float* __restrict__ bf,  float* __restrict__ out)
{
    extern __shared__ char smem[];
    const int tid   = threadIdx.x;
    const int lane  = tid & 31;
    const int w     = tid >> 5;
    const int mrow0 = (w >> 1) << 5;       // warp's 32 output rows
    const int nhalf = w & 1;
    const int ncol0 = nhalf << 6;          // warp's 64 output cols
    const int pid   = 1 + (w >> 1);        // named barrier id per warp pair
    const int grp   = lane >> 2, qd = lane & 3;
    const int tb    = blockIdx.x * TILE_M;
    const uint32_t sb   = smem_u32(smem);
    const uint32_t actA = sb + OFF_ACTA;

    float* outst = reinterpret_cast<float*>(smem + OFF_OUTST);
    float* zs    = reinterpret_cast<float*>(smem + OFF_ZS);
    float* mt    = reinterpret_cast<float*>(smem + OFF_MT);
    float* wicA  = reinterpret_cast<float*>(smem + OFF_WIC);
    float* wfs   = reinterpret_cast<float*>(smem + OFF_WFS);
    float* bis   = reinterpret_cast<float*>(smem + OFF_BIS);
    float* bs1s  = reinterpret_cast<float*>(smem + OFF_BS1);
    float* bs2s  = reinterpret_cast<float*>(smem + OFF_BS2);
    float* part  = reinterpret_cast<float*>(smem + OFF_PART);

    // ---- one-time preloads ----
    // Ws1/Ws2 -> bf16 SW128 tiles
    #pragma unroll 4
    for (int it = 0; it < 32; it++) {
        int p = it * NTH + tid;                 // pair index 0..8191
        int n = p >> 6, kp = p & 63;
        float2 a = __ldg(reinterpret_cast<const float2*>(Ws1) + (n << 6) + kp);
        float2 b = __ldg(reinterpret_cast<const float2*>(Ws2) + (n << 6) + kp);
        uint32_t o = act_off(n, kp * 2);
        sts32(sb + OFF_WS1 + o, pack2(a.x, a.y));
        sts32(sb + OFF_WS2 + o, pack2(b.x, b.y));
    }
    // z and out-state (stride-65 padded), M^T
    #pragma unroll 4
    for (int it = 0; it < 32; it++) {
        int idx = it * NTH + tid;               // 0..8191
        int r = idx >> 6, c = idx & 63;
        zs[r * 65 + c]    = __ldg(z + (size_t)tb * 64 + idx);
        outst[r * 65 + c] = __ldg(x + (size_t)tb * 64 + idx);
    }
    #pragma unroll 4
    for (int it = 0; it < 16; it++) {
        int idx = it * NTH + tid;               // 0..4095 ; mt[i*64+j] = M[j][i]
        mt[idx] = __ldg(Mg + ((idx & 63) << 6) + (idx >> 6));
    }
    if (tid < 128) {
        bs1s[tid] = __ldg(bs1 + tid);
        bs2s[tid] = __ldg(bs2 + tid);
    }
    load_wi(Wi, 0, sb, smem, 0, tid);           // Wi buffer for step 0
    __syncthreads();

    float acc[16][4];

    #pragma unroll 1
    for (int i = 0; i < 64; i++) {
        const int cur = i & 1;
        // ---- per-step small loads ----
        if (tid < 128) {
            wfs[tid] = __ldg(wf + i * 128 + tid);
            bis[tid] = __ldg(bi + i * 128 + tid);
        }
        const float bfv = __ldg(bf + i);
        // ---- build xm = outst * M[:,i] into actA cols [0,64) (M diag = 0) ----
        {
            const int row = tid >> 1, h = tid & 1;
            const float* mrow = mt + i * 64;
            const float* orow = outst + row * 65;
            #pragma unroll
            for (int jj = 0; jj < 32; jj += 4) {
                int j = h * 32 + jj;
                float v0 = orow[j + 0] * mrow[j + 0];
                float v1 = orow[j + 1] * mrow[j + 1];
                float v2 = orow[j + 2] * mrow[j + 2];
                float v3 = orow[j + 3] * mrow[j + 3];
                sts_v2(actA + act_off(row, j), pack2(v0, v1), pack2(v2, v3));
            }
        }
        __syncthreads();

        // ---- GEMM1: acc = xm[.,0:64] @ Wi^T ----
        gemm_warp<4>(actA, sb + OFF_WIB + (uint32_t)cur * 16384u, mrow0, ncol0, lane, acc);
        // prefetch next step's Wi into the other buffer (overlaps via warp arbiter)
        if (i < 63) load_wi(Wi, i + 1, sb, smem, cur ^ 1, tid);
        PAIRBAR(pid);                            // sibling done reading xm region

        // ---- epi1: h1 = relu(acc + wic*z + bi) -> actA ----
        {
            const float* wic = wicA + cur * 128;
            #pragma unroll
            for (int mtl = 0; mtl < 2; mtl++) {
                int rA = mrow0 + 16 * mtl + grp, rB = rA + 8;
                float zA = zs[rA * 65 + i], zB = zs[rB * 65 + i];
                #pragma unroll
                for (int nt = 0; nt < 8; nt++) {
                    int c = ncol0 + 8 * nt + 2 * qd;
                    float w0 = wic[c], w1 = wic[c + 1];
                    float b0 = bis[c], b1 = bis[c + 1];
                    float* A = acc[mtl * 8 + nt];
                    float v0 = fmaxf(fmaf(w0, zA, A[0]) + b0, 0.f);
                    float v1 = fmaxf(fmaf(w1, zA, A[1]) + b1, 0.f);
                    float v2 = fmaxf(fmaf(w0, zB, A[2]) + b0, 0.f);
                    float v3 = fmaxf(fmaf(w1, zB, A[3]) + b1, 0.f);
                    sts32(actA + act_off(rA, c), pack2(v0, v1));
                    sts32(actA + act_off(rB, c), pack2(v2, v3));
                }
            }
        }
        PAIRBAR(pid);                            // sibling's h1 half visible

        // ---- GEMM2: acc = h1 @ Ws1^T (K=128) ----
        gemm_warp<8>(actA, sb + OFF_WS1, mrow0, ncol0, lane, acc);
        PAIRBAR(pid);                            // sibling done reading h1

        // ---- epi2: h2 = relu(acc + bs1) -> actA ----
        #pragma unroll
        for (int mtl = 0; mtl < 2; mtl++) {
            int rA = mrow0 + 16 * mtl + grp, rB = rA + 8;
            #pragma unroll
            for (int nt = 0; nt < 8; nt++) {
                int c = ncol0 + 8 * nt + 2 * qd;
                float b0 = bs1s[c], b1 = bs1s[c + 1];
                float* A = acc[mtl * 8 + nt];
                sts32(actA + act_off(rA, c), pack2(fmaxf(A[0] + b0, 0.f), fmaxf(A[1] + b1, 0.f)));
                sts32(actA + act_off(rB, c), pack2(fmaxf(A[2] + b0, 0.f), fmaxf(A[3] + b1, 0.f)));
            }
        }
        PAIRBAR(pid);                            // sibling's h2 half visible

        // ---- GEMM3: acc = h2 @ Ws2^T (K=128) ----
        gemm_warp<8>(actA, sb + OFF_WS2, mrow0, ncol0, lane, acc);

        // ---- epi3: o = sigmoid( wf . relu(acc + bs2) + bf ) ----
        #pragma unroll
        for (int mtl = 0; mtl < 2; mtl++) {
            float pA = 0.f, pB = 0.f;
            #pragma unroll
            for (int nt = 0; nt < 8; nt++) {
                int c = ncol0 + 8 * nt + 2 * qd;
                float w0 = wfs[c], w1 = wfs[c + 1];
                float b0 = bs2s[c], b1 = bs2s[c + 1];
                float* A = acc[mtl * 8 + nt];
                pA = fmaf(w0, fmaxf(A[0] + b0, 0.f), pA);
                pA = fmaf(w1, fmaxf(A[1] + b1, 0.f), pA);
                pB = fmaf(w0, fmaxf(A[2] + b0, 0.f), pB);
                pB = fmaf(w1, fmaxf(A[3] + b1, 0.f), pB);
            }
            pA += __shfl_xor_sync(0xffffffffu, pA, 1);
            pA += __shfl_xor_sync(0xffffffffu, pA, 2);
            pB += __shfl_xor_sync(0xffffffffu, pB, 1);
            pB += __shfl_xor_sync(0xffffffffu, pB, 2);
            if (qd == 0) {
                int rA = mrow0 + 16 * mtl + grp;
                part[nhalf * 128 + rA]     = pA;
                part[nhalf * 128 + rA + 8] = pB;
            }
        }
        PAIRBAR(pid);                            // both halves' partials in smem
        if (nhalf == 0) {
            int row = mrow0 + lane;              // 32 rows per pair
            float t = part[row] + part[128 + row] + bfv;
            outst[row * 65 + i] = 1.f / (1.f + __expf(-t));
        }
        __syncthreads();                         // out-state ready for next step
    }

    // ---- write final out (coalesced) ----
    #pragma unroll 4
    for (int it = 0; it < 32; it++) {
        int idx = it * NTH + tid;                // 0..8191
        out[(size_t)tb * 64 + idx] = outst[(idx >> 6) * 65 + (idx & 63)];
    }
}

extern "C" void kernel_launch(void* const* d_in, const int* in_sizes, int n_in,
                              void* d_out, int out_size) {
    const float* x   = (const float*)d_in[0];
    const float* z   = (const float*)d_in[1];
    const float* Mg  = (const float*)d_in[2];
    const float* Wi  = (const float*)d_in[3];
    const float* bi  = (const float*)d_in[4];
    const float* Ws1 = (const float*)d_in[5];
    const float* bs1 = (const float*)d_in[6];
    const float* Ws2 = (const float*)d_in[7];
    const float* bs2 = (const float*)d_in[8];
    const float* wf  = (const float*)d_in[9];
    const float* bf  = (const float*)d_in[10];
    float* out = (float*)d_out;

    const int B = in_sizes[0] / 64;              // 65536
    const int grid = B / TILE_M;                 // 512

    static bool attr_set = false;
    if (!attr_set) {
        cudaFuncSetAttribute(gen_causal_kernel,
                             cudaFuncAttributeMaxDynamicSharedMemorySize, SMEM_TOTAL);
        attr_set = true;
    }
    gen_causal_kernel<<<grid, NTH, SMEM_TOTAL>>>(x, z, Mg, Wi, bi, Ws1, bs1,
                                                 Ws2, bs2, wf, bf, out);
}

// round 6
// speedup vs baseline: 1.1438x; 1.1438x over previous
// Generator_causal on GB300 (compute_103 baseline: warp-level mma.sync bf16 + ldmatrix).
// CTA = 512 threads = 2 independent 128-row batch tiles (8 warps each), 64 sequential
// node-steps. Weights (Wi double-buffered, Ws1, Ws2) shared across tiles in SMEM.
// Out-state kept in bf16 smem; final sigmoid outputs streamed to gmem in f32 per step.
#include <cuda_runtime.h>
#include <cuda_bf16.h>
#include <cstdint>

#define NTH    512
#define TILE_M 128

// ---------------- SMEM map (bytes); matrix tiles 1024-aligned ----------------
#define OFF_ACTA   1024u      // 2 x (128x128 bf16 blocked SW128, 32768)
#define OFF_WIB    66560u     // 2 x (128x64 bf16 blocked SW128, 16384)
#define OFF_WS1    99328u     // 128x128 bf16 blocked SW128
#define OFF_WS2    132096u    // 128x128 bf16 blocked SW128
#define OFF_OUT    164864u    // 2 x (128x66 bf16 out-state, 16896)
#define OFF_MCOL   198656u    // 2 x 64 f32 (M column, double buffered)
#define OFF_WIC    199168u    // 2 x 128 f32 (Wi z-column, double buffered)
#define OFF_WFS    200192u    // 128 f32
#define OFF_BIS    200704u    // 128 f32
#define OFF_BS1    201216u    // 128 f32
#define OFF_BS2    201728u    // 128 f32
#define OFF_PART   202240u    // 2 x 256 f32 head partials
#define SMEM_TOTAL 204288u

// ---------------- helpers ----------------
__device__ __forceinline__ uint32_t smem_u32(const void* p) {
    uint32_t a;
    asm("{ .reg .u64 t; cvta.to.shared.u64 t, %1; cvt.u32.u64 %0, t; }" : "=r"(a) : "l"(p));
    return a;
}
// Blocked SW128 byte offset for [rows x K] bf16 K-major tile:
// atom = 8 rows x 64 bf16 (1024B), atom-column stride = 16 atoms (128 rows).
__device__ __forceinline__ uint32_t act_off(int m, int k) {
    uint32_t b = ((uint32_t)(m >> 3) + (uint32_t)(k >> 6) * 16u) * 1024u
               + (uint32_t)(m & 7) * 128u + (uint32_t)(k & 63) * 2u;
    return b ^ ((b >> 3) & 0x70u);
}
__device__ __forceinline__ uint32_t pack2(float a, float b) {
    __nv_bfloat162 t = __floats2bfloat162_rn(a, b);
    return *reinterpret_cast<uint32_t*>(&t);
}
__device__ __forceinline__ void sts32(uint32_t addr, uint32_t v) {
    asm volatile("st.shared.b32 [%0], %1;" :: "r"(addr), "r"(v) : "memory");
}
__device__ __forceinline__ void sts_v2(uint32_t addr, uint32_t lo, uint32_t hi) {
    asm volatile("st.shared.v2.b32 [%0], {%1, %2};" :: "r"(addr), "r"(lo), "r"(hi) : "memory");
}
__device__ __forceinline__ void sts_b16(uint32_t addr, uint16_t v) {
    asm volatile("st.shared.b16 [%0], %1;" :: "r"(addr), "h"(v) : "memory");
}
__device__ __forceinline__ uint32_t lds32(uint32_t addr) {
    uint32_t v;
    asm volatile("ld.shared.b32 %0, [%1];" : "=r"(v) : "r"(addr));
    return v;
}
__device__ __forceinline__ void ldsm4(uint32_t addr, uint32_t* r) {
    asm volatile("ldmatrix.sync.aligned.m8n8.x4.shared.b16 {%0,%1,%2,%3}, [%4];"
                 : "=r"(r[0]), "=r"(r[1]), "=r"(r[2]), "=r"(r[3]) : "r"(addr));
}
__device__ __forceinline__ void mma16816(float* c, const uint32_t* a, uint32_t b0, uint32_t b1) {
    asm volatile("mma.sync.aligned.m16n8k16.row.col.f32.bf16.bf16.f32 "
                 "{%0,%1,%2,%3}, {%4,%5,%6,%7}, {%8,%9}, {%0,%1,%2,%3};"
                 : "+f"(c[0]), "+f"(c[1]), "+f"(c[2]), "+f"(c[3])
                 : "r"(a[0]), "r"(a[1]), "r"(a[2]), "r"(a[3]), "r"(b0), "r"(b1));
}
#define PAIRBAR(id) asm volatile("bar.sync %0, 64;" :: "r"(id) : "memory")

// C[32x64] warp tile = A[mrow0..+31, 0..16K) @ W[ncol0..+63, 0..16K)^T
template<int KSTEPS>
__device__ __forceinline__ void gemm_warp(uint32_t aBase, uint32_t bBase,
                                          int mrow0, int ncol0, int lane,
                                          float acc[16][4]) {
    #pragma unroll
    for (int t = 0; t < 16; t++) {
        acc[t][0] = 0.f; acc[t][1] = 0.f; acc[t][2] = 0.f; acc[t][3] = 0.f;
    }
    const int lr = lane & 7, lt = (lane >> 3) & 1, lh = lane >> 4;
    #pragma unroll
    for (int ks = 0; ks < KSTEPS; ks++) {
        const int k0 = ks * 16;
        uint32_t a[2][4];
        #pragma unroll
        for (int mt = 0; mt < 2; mt++)
            ldsm4(aBase + act_off(mrow0 + 16 * mt + lr + lt * 8, k0 + lh * 8), a[mt]);
        #pragma unroll
        for (int nj = 0; nj < 4; nj++) {
            uint32_t b[4];
            ldsm4(bBase + act_off(ncol0 + 16 * nj + lr + lh * 8, k0 + lt * 8), b);
            #pragma unroll
            for (int mt = 0; mt < 2; mt++) {
                mma16816(acc[mt * 8 + 2 * nj],     a[mt], b[0], b[1]);
                mma16816(acc[mt * 8 + 2 * nj + 1], a[mt], b[2], b[3]);
            }
        }
    }
}

// Stream Wi[step] (128x65 f32, row-major) into bf16 SW128 tile `buf` + z-column.
__device__ __forceinline__ void load_wi(const float* __restrict__ Wi, int step,
                                        uint32_t sb, char* smem, int buf, int tid) {
    const float* src = Wi + (size_t)step * 8320;
    const uint32_t wib = sb + OFF_WIB + (uint32_t)buf * 16384u;
    float* wicb = reinterpret_cast<float*>(smem + OFF_WIC) + buf * 128;
    #pragma unroll
    for (int it = 0; it < 17; it++) {
        int idx = it * NTH + tid;
        if (idx < 8320) {
            float v = __ldg(src + idx);
            int n = idx / 65, k = idx - n * 65;
            if (k < 64) {
                __nv_bfloat16 h = __float2bfloat16_rn(v);
                sts_b16(wib + act_off(n, k), *reinterpret_cast<uint16_t*>(&h));
            } else {
                wicb[n] = v;
            }
        }
    }
}

__global__ void __launch_bounds__(NTH, 1)
gen_causal_kernel(const float* __restrict__ x,   const float* __restrict__ z,
                  const float* __restrict__ Mg,  const float* __restrict__ Wi,
                  const float* __restrict__ bi,  const float* __restrict__ Ws1,
                  const float* __restrict__ bs1, const float* __restrict__ Ws2,
                  const float* __restrict__ bs2, const float* __restrict__ wf,
                  const float* __restrict__ bf,  float* __restrict__ out)
{
    extern __shared__ char smem[];
    const int tid  = threadIdx.x;
    const int lane = tid & 31;
    const int w    = tid >> 5;
    const int tile = w >> 3;                    // 0 or 1
    const int wt   = w & 7;                     // warp within tile
    const int mrow0 = (wt >> 1) << 5;           // 32 output rows
    const int nhalf = wt & 1;
    const int ncol0 = nhalf << 6;               // 64 output cols
    const int pid   = 1 + (w >> 1);             // named barrier per warp pair (1..8)
    const int grp   = lane >> 2, qd = lane & 3;
    const int tb    = blockIdx.x * 2 * TILE_M + tile * TILE_M;
    const uint32_t sb   = smem_u32(smem);
    const uint32_t actT = sb + OFF_ACTA + (uint32_t)tile * 32768u;
    const uint32_t outT = sb + OFF_OUT  + (uint32_t)tile * 16896u;

    float* mcolA = reinterpret_cast<float*>(smem + OFF_MCOL);
    float* wicA  = reinterpret_cast<float*>(smem + OFF_WIC);
    float* wfs   = reinterpret_cast<float*>(smem + OFF_WFS);
    float* bis   = reinterpret_cast<float*>(smem + OFF_BIS);
    float* bs1s  = reinterpret_cast<float*>(smem + OFF_BS1);
    float* bs2s  = reinterpret_cast<float*>(smem + OFF_BS2);
    float* part  = reinterpret_cast<float*>(smem + OFF_PART) + tile * 256;

    // ---- one-time preloads ----
    #pragma unroll 4
    for (int it = 0; it < 16; it++) {           // Ws1/Ws2 -> bf16 SW128
        int p = it * NTH + tid;                 // float2-pair index 0..8191
        int n = p >> 6, kp = p & 63;
        float2 a = __ldg(reinterpret_cast<const float2*>(Ws1) + (n << 6) + kp);
        float2 b = __ldg(reinterpret_cast<const float2*>(Ws2) + (n << 6) + kp);
        uint32_t o = act_off(n, kp * 2);
        sts32(sb + OFF_WS1 + o, pack2(a.x, a.y));
        sts32(sb + OFF_WS2 + o, pack2(b.x, b.y));
    }
    #pragma unroll 4
    for (int it = 0; it < 32; it++) {           // out-state <- x (bf16, stride 66)
        int idx = it * NTH + tid;               // 0..16383, contiguous over both tiles
        int tl = idx >> 13, rem = idx & 8191;
        int r = rem >> 6, c = rem & 63;
        float v = __ldg(x + (size_t)blockIdx.x * 16384 + idx);
        __nv_bfloat16 h = __float2bfloat16_rn(v);
        sts_b16(sb + OFF_OUT + (uint32_t)tl * 16896u + (uint32_t)(r * 66 + c) * 2u,
                *reinterpret_cast<uint16_t*>(&h));
    }
    if (tid < 64)  mcolA[tid] = __ldg(Mg + tid * 64);   // column 0
    if (tid < 128) {
        bs1s[tid] = __ldg(bs1 + tid);
        bs2s[tid] = __ldg(bs2 + tid);
    }
    load_wi(Wi, 0, sb, smem, 0, tid);
    __syncthreads();

    float acc[16][4];

    #pragma unroll 1
    for (int i = 0; i < 64; i++) {
        const int cur = i & 1;
        // ---- per-step small loads (visible after bar A) ----
        if (tid < 128) {
            wfs[tid] = __ldg(wf + i * 128 + tid);
            bis[tid] = __ldg(bi + i * 128 + tid);
        }
        if (tid < 64 && i < 63)
            mcolA[((i + 1) & 1) * 64 + tid] = __ldg(Mg + tid * 64 + i + 1);
        const float bfv = __ldg(bf + i);
        // z values this thread needs in epi1 (rows mrow0+grp+{0,8,16,24})
        float zr[4];
        #pragma unroll
        for (int kq = 0; kq < 4; kq++)
            zr[kq] = __ldg(z + (size_t)(tb + mrow0 + grp + 8 * kq) * 64 + i);

        // ---- build xm = bf16(outst) * M[:,i] into actT cols [0,64) ----
        {
            const int tt = tid & 255;
            const int row = tt >> 1, h = tt & 1;
            const float* mcol = mcolA + cur * 64;
            const uint32_t orow = outT + (uint32_t)row * 132u;
            #pragma unroll
            for (int jj = 0; jj < 32; jj += 4) {
                int j = h * 32 + jj;
                uint32_t p0 = lds32(orow + j * 2);          // bf16x2 {j, j+1}
                uint32_t p1 = lds32(orow + j * 2 + 4);      // bf16x2 {j+2, j+3}
                __nv_bfloat162 b0 = *reinterpret_cast<__nv_bfloat162*>(&p0);
                __nv_bfloat162 b1 = *reinterpret_cast<__nv_bfloat162*>(&p1);
                float v0 = __bfloat162float(b0.x) * mcol[j + 0];
                float v1 = __bfloat162float(b0.y) * mcol[j + 1];
                float v2 = __bfloat162float(b1.x) * mcol[j + 2];
                float v3 = __bfloat162float(b1.y) * mcol[j + 3];
                sts_v2(actT + act_off(row, j), pack2(v0, v1), pack2(v2, v3));
            }
        }
        __syncthreads();                        // bar A: xm + small vecs visible

        // ---- GEMM1: acc = xm[.,0:64] @ Wi_i^T ----
        gemm_warp<4>(actT, sb + OFF_WIB + (uint32_t)cur * 16384u, mrow0, ncol0, lane, acc);
        // prefetch next Wi into other buffer (readers of that buffer all passed bar A)
        if (i < 63) load_wi(Wi, i + 1, sb, smem, cur ^ 1, tid);
        PAIRBAR(pid);                           // pair done reading xm rows

        // ---- epi1: h1 = relu(acc + wic*z + bi) -> actT ----
        {
            const float* wic = wicA + cur * 128;
            #pragma unroll
            for (int mtl = 0; mtl < 2; mtl++) {
                int rA = mrow0 + 16 * mtl + grp, rB = rA + 8;
                float zA = zr[2 * mtl], zB = zr[2 * mtl + 1];
                #pragma unroll
                for (int nt = 0; nt < 8; nt++) {
                    int c = ncol0 + 8 * nt + 2 * qd;
                    float w0 = wic[c], w1 = wic[c + 1];
                    float b0 = bis[c], b1 = bis[c + 1];
                    float* A = acc[mtl * 8 + nt];
                    float v0 = fmaxf(fmaf(w0, zA, A[0]) + b0, 0.f);
                    float v1 = fmaxf(fmaf(w1, zA, A[1]) + b1, 0.f);
                    float v2 = fmaxf(fmaf(w0, zB, A[2]) + b0, 0.f);
                    float v3 = fmaxf(fmaf(w1, zB, A[3]) + b1, 0.f);
                    sts32(actT + act_off(rA, c), pack2(v0, v1));
                    sts32(actT + act_off(rB, c), pack2(v2, v3));
                }
            }
        }
        PAIRBAR(pid);                           // pair's h1 rows complete

        // ---- GEMM2: acc = h1 @ Ws1^T (K=128) ----
        gemm_warp<8>(actT, sb + OFF_WS1, mrow0, ncol0, lane, acc);
        PAIRBAR(pid);                           // pair done reading h1 rows

        // ---- epi2: h2 = relu(acc + bs1) -> actT ----
        #pragma unroll
        for (int mtl = 0; mtl < 2; mtl++) {
            int rA = mrow0 + 16 * mtl + grp, rB = rA + 8;
            #pragma unroll
            for (int nt = 0; nt < 8; nt++) {
                int c = ncol0 + 8 * nt + 2 * qd;
                float b0 = bs1s[c], b1 = bs1s[c + 1];
                float* A = acc[mtl * 8 + nt];
                sts32(actT + act_off(rA, c), pack2(fmaxf(A[0] + b0, 0.f), fmaxf(A[1] + b1, 0.f)));
                sts32(actT + act_off(rB, c), pack2(fmaxf(A[2] + b0, 0.f), fmaxf(A[3] + b1, 0.f)));
            }
        }
        PAIRBAR(pid);                           // pair's h2 rows complete

        // ---- GEMM3: acc = h2 @ Ws2^T (K=128) ----
        gemm_warp<8>(actT, sb + OFF_WS2, mrow0, ncol0, lane, acc);

        // ---- epi3: o = sigmoid( wf . relu(acc + bs2) + bf ) ----
        #pragma unroll
        for (int mtl = 0; mtl < 2; mtl++) {
            float pA = 0.f, pB = 0.f;
            #pragma unroll
            for (int nt = 0; nt < 8; nt++) {
                int c = ncol0 + 8 * nt + 2 * qd;
                float w0 = wfs[c], w1 = wfs[c + 1];
                float b0 = bs2s[c], b1 = bs2s[c + 1];
                float* A = acc[mtl * 8 + nt];
                pA = fmaf(w0, fmaxf(A[0] + b0, 0.f), pA);
                pA = fmaf(w1, fmaxf(A[1] + b1, 0.f), pA);
                pB = fmaf(w0, fmaxf(A[2] + b0, 0.f), pB);
                pB = fmaf(w1, fmaxf(A[3] + b1, 0.f), pB);
            }
            pA += __shfl_xor_sync(0xffffffffu, pA, 1);
            pA += __shfl_xor_sync(0xffffffffu, pA, 2);
            pB += __shfl_xor_sync(0xffffffffu, pB, 1);
            pB += __shfl_xor_sync(0xffffffffu, pB, 2);
            if (qd == 0) {
                int rA = mrow0 + 16 * mtl + grp;
                part[nhalf * 128 + rA]     = pA;
                part[nhalf * 128 + rA + 8] = pB;
            }
        }
        PAIRBAR(pid);                           // both halves' partials in smem
        if (nhalf == 0) {
            int row = mrow0 + lane;
            float t = part[row] + part[128 + row] + bfv;
            float o = 1.f / (1.f + __expf(-t));
            __nv_bfloat16 h = __float2bfloat16_rn(o);
            sts_b16(outT + (uint32_t)(row * 66 + i) * 2u, *reinterpret_cast<uint16_t*>(&h));
            out[(size_t)(tb + row) * 64 + i] = o;   // exact f32 final output
        }
        __syncthreads();                        // bar B: out-state + Wi buffer ready
    }
}

extern "C" void kernel_launch(void* const* d_in, const int* in_sizes, int n_in,
                              void* d_out, int out_size) {
    const float* x   = (const float*)d_in[0];
    const float* z   = (const float*)d_in[1];
    const float* Mg  = (const float*)d_in[2];
    const float* Wi  = (const float*)d_in[3];
    const float* bi  = (const float*)d_in[4];
    const float* Ws1 = (const float*)d_in[5];
    const float* bs1 = (const float*)d_in[6];
    const float* Ws2 = (const float*)d_in[7];
    const float* bs2 = (const float*)d_in[8];
    const float* wf  = (const float*)d_in[9];
    const float* bf  = (const float*)d_in[10];
    float* out = (float*)d_out;

    const int B = in_sizes[0] / 64;              // 65536
    const int grid = B / (2 * TILE_M);           // 256

    static bool attr_set = false;
    if (!attr_set) {
        cudaFuncSetAttribute(gen_causal_kernel,
                             cudaFuncAttributeMaxDynamicSharedMemorySize, SMEM_TOTAL);
        attr_set = true;
    }
    gen_causal_kernel<<<grid, NTH, SMEM_TOTAL>>>(x, z, Mg, Wi, bi, Ws1, bs1,
                                                 Ws2, bs2, wf, bf, out);
}

// round 7
// speedup vs baseline: 1.2690x; 1.1094x over previous
// Generator_causal on GB300 (compute_103 baseline): warp-level FP8 e4m3 mma.sync +
// ldmatrix. CTA = 512 threads = 2 DECOUPLED 128-row batch tiles (8 warps each,
// per-tile named barriers), 64 sequential node-steps. Activations/weights scaled
// x16 into e4m3; all accumulation f32 (acc = 256 x true). Wi pre-swizzled to fp8
// in a device scratch by a prologue kernel.
#include <cuda_runtime.h>
#include <cuda_bf16.h>
#include <cstdint>

#define NTH    512
#define TILE_M 128

// device scratch: pre-swizzled fp8(16*Wi) tiles + 16*z-column weights
__device__ __align__(16) uint8_t g_wi8[64][16384];
__device__ float g_wic16[64][128];

// ---------------- SMEM map (bytes) ----------------
#define OFF_ACT    1024u      // 2 tiles x 2 bufs (A,B) x 16384 fp8 = 65536
#define OFF_WIB    66560u     // 2 tiles x 2 bufs x 16384 = 65536
#define OFF_WS1    132096u    // 128x128 fp8 swizzled = 16384
#define OFF_WS2    148480u    // 16384
#define OFF_OUT    164864u    // 2 x (128x66 bf16) = 33792
#define OFF_VEC    198656u    // 2 x 4096 (mcol16[2][64]|wic16[2][128]|wfs|bis16|part)
#define OFF_BS1    206848u    // 128 f32 (16*bs1)
#define OFF_BS2    207360u    // 128 f32 (bs2)
#define SMEM_TOTAL 207872u

// ---------------- helpers ----------------
__device__ __forceinline__ uint32_t smem_u32(const void* p) {
    uint32_t a;
    asm("{ .reg .u64 t; cvta.to.shared.u64 t, %1; cvt.u32.u64 %0, t; }" : "=r"(a) : "l"(p));
    return a;
}
// fp8 tile byte offset: 128B rows, 16B-chunk XOR swizzle. k in BYTES (fp8 index).
__device__ __forceinline__ uint32_t off8b(int m, int k) {
    return (uint32_t)m * 128u + ((uint32_t)k ^ (((uint32_t)m & 7u) * 16u));
}
// same, k in b16 units (pairs of fp8)
__device__ __forceinline__ uint32_t off8u(int m, int u) {
    return (uint32_t)m * 128u + (((uint32_t)u * 2u) ^ (((uint32_t)m & 7u) * 16u));
}
__device__ __forceinline__ uint16_t pk2_e4m3(float lo, float hi) {
    uint16_t r;
    asm("cvt.rn.satfinite.e4m3x2.f32 %0, %1, %2;" : "=h"(r) : "f"(hi), "f"(lo));
    return r;
}
__device__ __forceinline__ uint32_t pk4_e4m3(float v0, float v1, float v2, float v3) {
    uint16_t lo = pk2_e4m3(v0, v1), hi = pk2_e4m3(v2, v3);
    uint32_t r;
    asm("mov.b32 %0, {%1, %2};" : "=r"(r) : "h"(lo), "h"(hi));
    return r;
}
__device__ __forceinline__ uint8_t fp8b(float v) {
    return (uint8_t)pk2_e4m3(v, 0.f);
}
__device__ __forceinline__ void sts32(uint32_t addr, uint32_t v) {
    asm volatile("st.shared.b32 [%0], %1;" :: "r"(addr), "r"(v) : "memory");
}
__device__ __forceinline__ void sts_b16(uint32_t addr, uint16_t v) {
    asm volatile("st.shared.b16 [%0], %1;" :: "r"(addr), "h"(v) : "memory");
}
__device__ __forceinline__ void sts128(uint32_t addr, uint4 v) {
    asm volatile("st.shared.v4.b32 [%0], {%1,%2,%3,%4};"
                 :: "r"(addr), "r"(v.x), "r"(v.y), "r"(v.z), "r"(v.w) : "memory");
}
__device__ __forceinline__ uint32_t lds32(uint32_t addr) {
    uint32_t v;
    asm volatile("ld.shared.b32 %0, [%1];" : "=r"(v) : "r"(addr));
    return v;
}
__device__ __forceinline__ void ldsm4(uint32_t addr, uint32_t* r) {
    asm volatile("ldmatrix.sync.aligned.m8n8.x4.shared.b16 {%0,%1,%2,%3}, [%4];"
                 : "=r"(r[0]), "=r"(r[1]), "=r"(r[2]), "=r"(r[3]) : "r"(addr));
}
__device__ __forceinline__ void mma_fp8(float* c, const uint32_t* a, uint32_t b0, uint32_t b1) {
    asm volatile("mma.sync.aligned.m16n8k32.row.col.f32.e4m3.e4m3.f32 "
                 "{%0,%1,%2,%3}, {%4,%5,%6,%7}, {%8,%9}, {%0,%1,%2,%3};"
                 : "+f"(c[0]), "+f"(c[1]), "+f"(c[2]), "+f"(c[3])
                 : "r"(a[0]), "r"(a[1]), "r"(a[2]), "r"(a[3]), "r"(b0), "r"(b1));
}
#define TILEBAR(t)  asm volatile("bar.sync %0, 256;" :: "r"(1 + (t)) : "memory")
#define PAIRBAR(id) asm volatile("bar.sync %0, 64;"  :: "r"(id) : "memory")

// C[32x64] warp tile = A[mrow0..+31, :] @ W[ncol0..+63, :]^T, K = KSTEPS*32 fp8
template<int KSTEPS>
__device__ __forceinline__ void gemm8(uint32_t aBase, uint32_t bBase,
                                      int mrow0, int ncol0, int lane,
                                      float acc[16][4]) {
    #pragma unroll
    for (int t = 0; t < 16; t++) {
        acc[t][0] = 0.f; acc[t][1] = 0.f; acc[t][2] = 0.f; acc[t][3] = 0.f;
    }
    const int lr = lane & 7, lt = (lane >> 3) & 1, lh = lane >> 4;
    #pragma unroll
    for (int ks = 0; ks < KSTEPS; ks++) {
        const int k0 = ks * 16;                       // b16 units
        uint32_t a[2][4];
        #pragma unroll
        for (int mt = 0; mt < 2; mt++)
            ldsm4(aBase + off8u(mrow0 + 16 * mt + lr + lt * 8, k0 + lh * 8), a[mt]);
        #pragma unroll
        for (int nj = 0; nj < 4; nj++) {
            uint32_t b[4];
            ldsm4(bBase + off8u(ncol0 + 16 * nj + lr + lh * 8, k0 + lt * 8), b);
            #pragma unroll
            for (int mt = 0; mt < 2; mt++) {
                mma_fp8(acc[mt * 8 + 2 * nj],     a[mt], b[0], b[1]);
                mma_fp8(acc[mt * 8 + 2 * nj + 1], a[mt], b[2], b[3]);
            }
        }
    }
}

// ---------------- prologue: convert Wi to pre-swizzled fp8(16*w) ----------------
__global__ void prep_wi_kernel(const float* __restrict__ Wi) {
    const int s = blockIdx.x;
    const float* src = Wi + (size_t)s * 8320;
    for (int idx = threadIdx.x; idx < 8320; idx += 256) {
        int n = idx / 65, k = idx - n * 65;
        float v = __ldg(src + idx) * 16.f;
        if (k < 64) g_wi8[s][off8b(n, k)] = fp8b(v);
        else        g_wic16[s][n] = v;
    }
}

// ---------------- main kernel ----------------
__global__ void __launch_bounds__(NTH, 1)
gen_causal_kernel(const float* __restrict__ x,   const float* __restrict__ z,
                  const float* __restrict__ Mg,  const float* __restrict__ bi,
                  const float* __restrict__ Ws1, const float* __restrict__ bs1,
                  const float* __restrict__ Ws2, const float* __restrict__ bs2,
                  const float* __restrict__ wf,  const float* __restrict__ bf,
                  float* __restrict__ out)
{
    extern __shared__ char smem[];
    const int tid  = threadIdx.x;
    const int lane = tid & 31;
    const int w    = tid >> 5;
    const int tile = w >> 3;                    // 0 or 1
    const int wt   = w & 7;
    const int tt   = tid & 255;                 // thread within tile
    const int mrow0 = (wt >> 1) << 5;           // warp's 32 output rows
    const int nhalf = wt & 1;
    const int ncol0 = nhalf << 6;               // warp's 64 output cols
    const int pid   = 3 + (w >> 1);             // pair barrier id (3..10)
    const int grp   = lane >> 2, qd = lane & 3;
    const int tb    = blockIdx.x * 2 * TILE_M + tile * TILE_M;
    const uint32_t sb   = smem_u32(smem);
    const uint32_t actA = sb + OFF_ACT + (uint32_t)tile * 32768u;       // xm / h2
    const uint32_t actB = actA + 16384u;                                 // h1
    const uint32_t wibT = sb + OFF_WIB + (uint32_t)tile * 32768u;
    const uint32_t outT = sb + OFF_OUT + (uint32_t)tile * 16896u;

    float* mcolT = reinterpret_cast<float*>(smem + OFF_VEC + tile * 4096); // [2][64]
    float* wicT  = mcolT + 128;                                            // [2][128]
    float* wfsT  = wicT + 256;                                             // [128]
    float* bisT  = wfsT + 128;                                             // [128] 16*bi
    float* partT = bisT + 128;                                             // [256]
    float* bs1s  = reinterpret_cast<float*>(smem + OFF_BS1);               // 16*bs1
    float* bs2s  = reinterpret_cast<float*>(smem + OFF_BS2);

    // ---- one-time init (all 512 threads) ----
    #pragma unroll 4
    for (int it = 0; it < 8; it++) {            // Ws1/Ws2 -> fp8(16*w), swizzled
        int q = it * NTH + tid;                 // float4 index 0..4095
        int n = q >> 5, k4 = (q & 31) * 4;
        float4 a = __ldg(reinterpret_cast<const float4*>(Ws1) + q);
        float4 b = __ldg(reinterpret_cast<const float4*>(Ws2) + q);
        uint32_t o = off8b(n, k4);
        sts32(sb + OFF_WS1 + o, pk4_e4m3(16.f * a.x, 16.f * a.y, 16.f * a.z, 16.f * a.w));
        sts32(sb + OFF_WS2 + o, pk4_e4m3(16.f * b.x, 16.f * b.y, 16.f * b.z, 16.f * b.w));
    }
    #pragma unroll 4
    for (int it = 0; it < 32; it++) {           // out-state <- x (bf16, stride 66)
        int idx = it * NTH + tid;               // 0..16383 over both tiles
        int tl = idx >> 13, rem = idx & 8191;
        int r = rem >> 6, c = rem & 63;
        float v = __ldg(x + (size_t)blockIdx.x * 16384 + idx);
        __nv_bfloat16 h = __float2bfloat16_rn(v);
        sts_b16(sb + OFF_OUT + (uint32_t)tl * 16896u + (uint32_t)(r * 66 + c) * 2u,
                *reinterpret_cast<uint16_t*>(&h));
    }
    // per-tile: Wi buffer 0 + wic 0 + mcol 0
    #pragma unroll
    for (int it = 0; it < 4; it++) {
        int o = (it * 256 + tt) * 16;
        uint4 v = *reinterpret_cast<const uint4*>(g_wi8[0] + o);
        sts128(wibT + o, v);
    }
    if (tt < 128) wicT[tt] = g_wic16[0][tt];
    if (tt < 64)  mcolT[tt] = 16.f * __ldg(Mg + tt * 64);
    if (tid < 128) {
        bs1s[tid] = 16.f * __ldg(bs1 + tid);
        bs2s[tid] = __ldg(bs2 + tid);
    }
    __syncthreads();

    float acc[16][4];

    #pragma unroll 1
    for (int i = 0; i < 64; i++) {
        const int cur = i & 1;
        // ---- per-step small loads ----
        if (tt < 128) {
            wfsT[tt] = __ldg(wf + i * 128 + tt);
            bisT[tt] = 16.f * __ldg(bi + i * 128 + tt);
        }
        if (tt < 64 && i < 63)
            mcolT[((i + 1) & 1) * 64 + tt] = 16.f * __ldg(Mg + tt * 64 + i + 1);
        const float bfv = __ldg(bf + i);
        float zr[4];
        #pragma unroll
        for (int kq = 0; kq < 4; kq++)
            zr[kq] = __ldg(z + (size_t)(tb + mrow0 + grp + 8 * kq) * 64 + i);

        // ---- build xm16 = 16 * outst * M[:,i] -> actA fp8 cols [0,64) ----
        {
            const int row = tt >> 1, h = tt & 1;
            const float* mc = mcolT + cur * 64;
            const uint32_t orow = outT + (uint32_t)row * 132u;
            #pragma unroll
            for (int jj = 0; jj < 32; jj += 4) {
                int j = h * 32 + jj;
                uint32_t p0 = lds32(orow + j * 2);
                uint32_t p1 = lds32(orow + j * 2 + 4);
                __nv_bfloat162 b0 = *reinterpret_cast<__nv_bfloat162*>(&p0);
                __nv_bfloat162 b1 = *reinterpret_cast<__nv_bfloat162*>(&p1);
                float v0 = __bfloat162float(b0.x) * mc[j + 0];
                float v1 = __bfloat162float(b0.y) * mc[j + 1];
                float v2 = __bfloat162float(b1.x) * mc[j + 2];
                float v3 = __bfloat162float(b1.y) * mc[j + 3];
                sts32(actA + off8b(row, j), pk4_e4m3(v0, v1, v2, v3));
            }
        }
        TILEBAR(tile);                           // xm + vecs visible tile-wide

        // ---- GEMM1: acc = xm @ Wi^T (K=64 fp8 -> 2 ksteps) ----
        gemm8<2>(actA, wibT + (uint32_t)cur * 16384u, mrow0, ncol0, lane, acc);
        // prefetch next step's Wi into other buffer (safe: readers passed TILEBAR)
        if (i < 63) {
            const uint8_t* srcw = g_wi8[i + 1];
            uint32_t dst = wibT + (uint32_t)(cur ^ 1) * 16384u;
            #pragma unroll
            for (int it = 0; it < 4; it++) {
                int o = (it * 256 + tt) * 16;
                uint4 v = *reinterpret_cast<const uint4*>(srcw + o);
                sts128(dst + o, v);
            }
            if (tt < 128) wicT[(cur ^ 1) * 128 + tt] = g_wic16[i + 1][tt];
        }

        // ---- epi1: h1_16 = relu(acc/16 + wic16*z + bi16) -> actB (no bar needed) ----
        {
            const float* wic = wicT + cur * 128;
            #pragma unroll
            for (int mtl = 0; mtl < 2; mtl++) {
                int rA = mrow0 + 16 * mtl + grp, rB = rA + 8;
                float zA = zr[2 * mtl], zB = zr[2 * mtl + 1];
                #pragma unroll
                for (int nt = 0; nt < 8; nt++) {
                    int c = ncol0 + 8 * nt + 2 * qd;
                    float w0 = wic[c], w1 = wic[c + 1];
                    float b0 = bisT[c], b1 = bisT[c + 1];
                    float* A = acc[mtl * 8 + nt];
                    float v0 = fmaxf(fmaf(A[0], 0.0625f, fmaf(w0, zA, b0)), 0.f);
                    float v1 = fmaxf(fmaf(A[1], 0.0625f, fmaf(w1, zA, b1)), 0.f);
                    float v2 = fmaxf(fmaf(A[2], 0.0625f, fmaf(w0, zB, b0)), 0.f);
                    float v3 = fmaxf(fmaf(A[3], 0.0625f, fmaf(w1, zB, b1)), 0.f);
                    sts_b16(actB + off8b(rA, c), pk2_e4m3(v0, v1));
                    sts_b16(actB + off8b(rB, c), pk2_e4m3(v2, v3));
                }
            }
        }
        TILEBAR(tile);                           // h1 complete tile-wide

        // ---- GEMM2: acc = h1 @ Ws1^T (K=128 fp8 -> 4 ksteps) ----
        gemm8<4>(actB, sb + OFF_WS1, mrow0, ncol0, lane, acc);

        // ---- epi2: h2_16 = relu(acc/16 + bs1_16) -> actA (no bar needed) ----
        #pragma unroll
        for (int mtl = 0; mtl < 2; mtl++) {
            int rA = mrow0 + 16 * mtl + grp, rB = rA + 8;
            #pragma unroll
            for (int nt = 0; nt < 8; nt++) {
                int c = ncol0 + 8 * nt + 2 * qd;
                float b0 = bs1s[c], b1 = bs1s[c + 1];
                float* A = acc[mtl * 8 + nt];
                float v0 = fmaxf(fmaf(A[0], 0.0625f, b0), 0.f);
                float v1 = fmaxf(fmaf(A[1], 0.0625f, b1), 0.f);
                float v2 = fmaxf(fmaf(A[2], 0.0625f, b0), 0.f);
                float v3 = fmaxf(fmaf(A[3], 0.0625f, b1), 0.f);
                sts_b16(actA + off8b(rA, c), pk2_e4m3(v0, v1));
                sts_b16(actA + off8b(rB, c), pk2_e4m3(v2, v3));
            }
        }
        TILEBAR(tile);                           // h2 complete tile-wide

        // ---- GEMM3: acc = h2 @ Ws2^T ----
        gemm8<4>(actA, sb + OFF_WS2, mrow0, ncol0, lane, acc);

        // ---- epi3: o = sigmoid( wf . relu(acc/256 + bs2) + bf ) ----
        #pragma unroll
        for (int mtl = 0; mtl < 2; mtl++) {
            float pA = 0.f, pB = 0.f;
            #pragma unroll
            for (int nt = 0; nt < 8; nt++) {
                int c = ncol0 + 8 * nt + 2 * qd;
                float w0 = wfsT[c], w1 = wfsT[c + 1];
                float b0 = bs2s[c], b1 = bs2s[c + 1];
                float* A = acc[mtl * 8 + nt];
                pA = fmaf(w0, fmaxf(fmaf(A[0], 0.00390625f, b0), 0.f), pA);
                pA = fmaf(w1, fmaxf(fmaf(A[1], 0.00390625f, b1), 0.f), pA);
                pB = fmaf(w0, fmaxf(fmaf(A[2], 0.00390625f, b0), 0.f), pB);
                pB = fmaf(w1, fmaxf(fmaf(A[3], 0.00390625f, b1), 0.f), pB);
            }
            pA += __shfl_xor_sync(0xffffffffu, pA, 1);
            pA += __shfl_xor_sync(0xffffffffu, pA, 2);
            pB += __shfl_xor_sync(0xffffffffu, pB, 1);
            pB += __shfl_xor_sync(0xffffffffu, pB, 2);
            if (qd == 0) {
                int rA = mrow0 + 16 * mtl + grp;
                partT[nhalf * 128 + rA]     = pA;
                partT[nhalf * 128 + rA + 8] = pB;
            }
        }
        PAIRBAR(pid);
        if (nhalf == 0) {
            int row = mrow0 + lane;
            float t = partT[row] + partT[128 + row] + bfv;
            float o = 1.f / (1.f + __expf(-t));
            __nv_bfloat16 h = __float2bfloat16_rn(o);
            sts_b16(outT + (uint32_t)(row * 66 + i) * 2u, *reinterpret_cast<uint16_t*>(&h));
            out[(size_t)(tb + row) * 64 + i] = o;    // exact f32 output
        }
        TILEBAR(tile);                           // end of step: act/out/Wi buf safe
    }
}

extern "C" void kernel_launch(void* const* d_in, const int* in_sizes, int n_in,
                              void* d_out, int out_size) {
    const float* x   = (const float*)d_in[0];
    const float* z   = (const float*)d_in[1];
    const float* Mg  = (const float*)d_in[2];
    const float* Wi  = (const float*)d_in[3];
    const float* bi  = (const float*)d_in[4];
    const float* Ws1 = (const float*)d_in[5];
    const float* bs1 = (const float*)d_in[6];
    const float* Ws2 = (const float*)d_in[7];
    const float* bs2 = (const float*)d_in[8];
    const float* wf  = (const float*)d_in[9];
    const float* bf  = (const float*)d_in[10];
    float* out = (float*)d_out;

    const int B = in_sizes[0] / 64;              // 65536
    const int grid = B / (2 * TILE_M);           // 256

    cudaFuncSetAttribute(gen_causal_kernel,
                         cudaFuncAttributeMaxDynamicSharedMemorySize, SMEM_TOTAL);
    prep_wi_kernel<<<64, 256>>>(Wi);
    gen_causal_kernel<<<grid, NTH, SMEM_TOTAL>>>(x, z, Mg, bi, Ws1, bs1,
                                                 Ws2, bs2, wf, bf, out);
}